// round 15
// baseline (speedup 1.0000x reference)
#include <cuda_runtime.h>
#include <cuda_fp16.h>
#include <cstdint>

#define NN 50000
#define EE 800000
#define DD 200
#define RR 500
#define KP 400           // fused K: [agg 0..199][h 200..399]
#define HOFF 200
#define BM 128
#define BN 208
#define NT 25            // 25 k-chunks (single fp16 pass)
#define SLOPE 0.22916666666666666f
#define NB 196           // ceil(NN/256)
#define AGG_B 10000      // NN/5 agg blocks (5 nodes x 50 threads)
#define PREF_B 16

// ---------------- scratch (zero-initialized at load; invariants restored) ----
__device__ __align__(16) __half g_Af16[(size_t)NN * KP];   // fp16 A: agg | h
__device__ __align__(16) __half g_B16[2 * BN * KP];        // fp16 weights (fused, transposed)
__device__ __align__(16) __half g_rel16[RR * DD];          // fp16 relation embeddings
__device__ float g_relagg[(size_t)NN * DD];                // fp32 (feeds both layers)
__device__ float g_fixbuf[(size_t)NN * DD];
__device__ int g_indeg[NN];          // zero at entry (restored by s3_k)
__device__ int g_off[NN + 1];
__device__ int g_cur[NN];
__device__ int g_exc[NN];
__device__ int g_bsum[NB];
__device__ int g_bpre[NB];
__device__ unsigned int g_csr[EE];   // src | (etype<<16)
__device__ int g_list_no[NN];
__device__ int g_cnt[2];             // zeroed by s2_k each call

// ---------------- helpers -----------------------------------------------------
__device__ __forceinline__ uint32_t smem_u32(const void* p) {
    uint32_t a;
    asm("{ .reg .u64 t; cvta.to.shared.u64 t, %1; cvt.u32.u64 %0, t; }" : "=r"(a) : "l"(p));
    return a;
}
__device__ __forceinline__ void cp16(uint32_t d, const void* s) {
    asm volatile("cp.async.cg.shared.global [%0], [%1], 16;" :: "r"(d), "l"(s));
}
#define CP_COMMIT() asm volatile("cp.async.commit_group;")
#define CP_WAIT2()  asm volatile("cp.async.wait_group 2;")
__device__ __forceinline__ void ldsm4(uint32_t* r, uint32_t a) {
    asm volatile("ldmatrix.sync.aligned.m8n8.x4.shared.b16 {%0,%1,%2,%3}, [%4];"
                 : "=r"(r[0]), "=r"(r[1]), "=r"(r[2]), "=r"(r[3]) : "r"(a));
}
__device__ __forceinline__ void ldsm2(uint32_t* r, uint32_t a) {
    asm volatile("ldmatrix.sync.aligned.m8n8.x2.shared.b16 {%0,%1}, [%2];"
                 : "=r"(r[0]), "=r"(r[1]) : "r"(a));
}
__device__ __forceinline__ void mma16816(float* c, const uint32_t* a, uint32_t b0, uint32_t b1) {
    asm volatile(
        "mma.sync.aligned.m16n8k16.row.col.f32.f16.f16.f32 "
        "{%0,%1,%2,%3},{%4,%5,%6,%7},{%8,%9},{%0,%1,%2,%3};"
        : "+f"(c[0]), "+f"(c[1]), "+f"(c[2]), "+f"(c[3])
        : "r"(a[0]), "r"(a[1]), "r"(a[2]), "r"(a[3]), "r"(b0), "r"(b1));
}

// ---------------- setup kernels ----------------------------------------------
__global__ void count_k(const int* __restrict__ dst) {
    int e = blockIdx.x * blockDim.x + threadIdx.x;
    if (e < EE) atomicAdd(&g_indeg[dst[e]], 1);
}
__global__ void s1_k() {
    int b = blockIdx.x, t = threadIdx.x, i = b * 256 + t;
    int v = (i < NN) ? g_indeg[i] : 0;
    int lane = t & 31, w = t >> 5;
    int x = v;
#pragma unroll
    for (int o = 1; o < 32; o <<= 1) {
        int y = __shfl_up_sync(0xffffffffu, x, o);
        if (lane >= o) x += y;
    }
    __shared__ int ws[8];
    if (lane == 31) ws[w] = x;
    __syncthreads();
    if (w == 0) {
        int s = (lane < 8) ? ws[lane] : 0;
#pragma unroll
        for (int o = 1; o < 8; o <<= 1) {
            int y = __shfl_up_sync(0xffffffffu, s, o);
            if (lane >= o) s += y;
        }
        if (lane < 8) ws[lane] = s;
    }
    __syncthreads();
    int incl = x + (w > 0 ? ws[w - 1] : 0);
    if (i < NN) g_exc[i] = incl - v;
    if (t == 255) g_bsum[b] = incl;
}
__global__ void s2_k() {
    int t = threadIdx.x;
    if (t < 2) g_cnt[t] = 0;
    int v = (t < NB) ? g_bsum[t] : 0;
    int lane = t & 31, w = t >> 5;
    int x = v;
#pragma unroll
    for (int o = 1; o < 32; o <<= 1) {
        int y = __shfl_up_sync(0xffffffffu, x, o);
        if (lane >= o) x += y;
    }
    __shared__ int ws[8];
    if (lane == 31) ws[w] = x;
    __syncthreads();
    if (w == 0) {
        int s = (lane < 8) ? ws[lane] : 0;
#pragma unroll
        for (int o = 1; o < 8; o <<= 1) {
            int y = __shfl_up_sync(0xffffffffu, s, o);
            if (lane >= o) s += y;
        }
        if (lane < 8) ws[lane] = s;
    }
    __syncthreads();
    int incl = x + (w > 0 ? ws[w - 1] : 0);
    if (t < NB) g_bpre[t] = incl - v;
    if (t == NB - 1) g_off[NN] = incl;
}
__global__ void s3_k() {
    int b = blockIdx.x, t = threadIdx.x, i = b * 256 + t;
    if (i >= NN) return;
    int o = g_exc[i] + g_bpre[b];
    g_off[i] = o;
    g_cur[i] = o;
    if (g_indeg[i] == 0) {
        int p = atomicAdd(&g_cnt[1], 1);
        g_list_no[p] = i;
    }
    g_indeg[i] = 0;   // restore invariant for next call
}
// fused: fill (CSR) + init (A h-region) + wprep (fp16 weights) + rel fp16
#define FILL_B 3125
#define INIT_B 19532
#define WPREP_B 650
#define RELC_B 196
__global__ void setup_k(const int* __restrict__ src, const int* __restrict__ dst,
                        const int* __restrict__ et,
                        const float* __restrict__ emb, const int* __restrict__ node_id,
                        const float* __restrict__ wn, const float* __restrict__ wl,
                        const float* __restrict__ rel) {
    int b = blockIdx.x;
    if (b < FILL_B) {
        int e = b * 256 + threadIdx.x;
        if (e < EE) {
            int p = atomicAdd(&g_cur[dst[e]], 1);
            g_csr[p] = (unsigned int)src[e] | ((unsigned int)et[e] << 16);
        }
    } else if (b < FILL_B + INIT_B) {
        long idx = (long)(b - FILL_B) * 256 + threadIdx.x;
        if (idx >= (long)NN * (DD / 2)) return;
        int i = (int)(idx / (DD / 2));
        int c = (int)(idx - (long)i * (DD / 2)) * 2;
        const float* e = emb + (size_t)node_id[i] * DD + c;
        *(half2*)(g_Af16 + (size_t)i * KP + HOFF + c) = __floats2half2_rn(e[0], e[1]);
    } else if (b < FILL_B + INIT_B + WPREP_B) {
        int idx = (b - FILL_B - INIT_B) * 256 + threadIdx.x;
        if (idx >= 2 * BN * KP) return;
        int l = idx / (BN * KP);
        int rem = idx - l * BN * KP;
        int n = rem / KP;
        int k = rem - n * KP;
        float w = 0.f;
        if (n < DD) {
            if (k < DD) w = wn[(size_t)l * DD * DD + k * DD + n];
            else        w = wl[(size_t)l * DD * DD + (k - DD) * DD + n];
        }
        g_B16[idx] = __float2half_rn(w);
    } else {
        int idx = (b - FILL_B - INIT_B - WPREP_B) * 256 + threadIdx.x;
        if (idx >= RR * DD / 2) return;
        int c = idx * 2;
        *(half2*)(g_rel16 + c) = __floats2half2_rn(rel[c], rel[c + 1]);
    }
}

// ---------------- aggregate (+ fused indeg==0 prefix) ------------------------
// 5 nodes per 256-thread block: t<250, node = t/50, col quartet = (t%50)*4.
// 4-edge unrolled loop: loads batched (MLP=4), adds kept in edge order.
__global__ void agg_k(const float* __restrict__ norm, int first,
                      const float* __restrict__ wev) {
    if (blockIdx.x < AGG_B) {
        int t = threadIdx.x;
        if (t >= 250) return;
        int sub = t / 50;
        int tq = t - sub * 50;
        int i = blockIdx.x * 5 + sub;
        int c = tq * 4;
        int s0 = g_off[i], s1 = g_off[i + 1];
        float a0 = 0.f, a1 = 0.f, a2 = 0.f, a3 = 0.f;
        if (first) {
            float r0 = 0.f, r1 = 0.f, r2 = 0.f, r3 = 0.f;
            int p = s0;
            for (; p + 4 <= s1; p += 4) {
                unsigned int pe0 = g_csr[p + 0], pe1 = g_csr[p + 1];
                unsigned int pe2 = g_csr[p + 2], pe3 = g_csr[p + 3];
                int2 rv0 = *(const int2*)(g_rel16 + (size_t)(pe0 >> 16) * DD + c);
                int2 rv1 = *(const int2*)(g_rel16 + (size_t)(pe1 >> 16) * DD + c);
                int2 rv2 = *(const int2*)(g_rel16 + (size_t)(pe2 >> 16) * DD + c);
                int2 rv3 = *(const int2*)(g_rel16 + (size_t)(pe3 >> 16) * DD + c);
                int2 hv0 = *(const int2*)(g_Af16 + (size_t)(pe0 & 0xFFFF) * KP + HOFF + c);
                int2 hv1 = *(const int2*)(g_Af16 + (size_t)(pe1 & 0xFFFF) * KP + HOFF + c);
                int2 hv2 = *(const int2*)(g_Af16 + (size_t)(pe2 & 0xFFFF) * KP + HOFF + c);
                int2 hv3 = *(const int2*)(g_Af16 + (size_t)(pe3 & 0xFFFF) * KP + HOFF + c);
#define ACC_RH(rv, hv) { \
                float2 ra = __half22float2(*(half2*)&(rv).x), rb = __half22float2(*(half2*)&(rv).y); \
                float2 ha = __half22float2(*(half2*)&(hv).x), hb = __half22float2(*(half2*)&(hv).y); \
                r0 += ra.x; r1 += ra.y; r2 += rb.x; r3 += rb.y; \
                a0 += ha.x; a1 += ha.y; a2 += hb.x; a3 += hb.y; }
                ACC_RH(rv0, hv0) ACC_RH(rv1, hv1) ACC_RH(rv2, hv2) ACC_RH(rv3, hv3)
            }
            for (; p < s1; p++) {
                unsigned int pe = g_csr[p];
                int2 rv = *(const int2*)(g_rel16 + (size_t)(pe >> 16) * DD + c);
                int2 hv = *(const int2*)(g_Af16 + (size_t)(pe & 0xFFFF) * KP + HOFF + c);
                ACC_RH(rv, hv)
            }
#undef ACC_RH
            *(float4*)(g_relagg + (size_t)i * DD + c) = make_float4(r0, r1, r2, r3);
            a0 += r0; a1 += r1; a2 += r2; a3 += r3;
        } else {
            float4 r4 = *(const float4*)(g_relagg + (size_t)i * DD + c);
            a0 = r4.x; a1 = r4.y; a2 = r4.z; a3 = r4.w;
            int p = s0;
            for (; p + 4 <= s1; p += 4) {
                unsigned int pe0 = g_csr[p + 0], pe1 = g_csr[p + 1];
                unsigned int pe2 = g_csr[p + 2], pe3 = g_csr[p + 3];
                int2 hv0 = *(const int2*)(g_Af16 + (size_t)(pe0 & 0xFFFF) * KP + HOFF + c);
                int2 hv1 = *(const int2*)(g_Af16 + (size_t)(pe1 & 0xFFFF) * KP + HOFF + c);
                int2 hv2 = *(const int2*)(g_Af16 + (size_t)(pe2 & 0xFFFF) * KP + HOFF + c);
                int2 hv3 = *(const int2*)(g_Af16 + (size_t)(pe3 & 0xFFFF) * KP + HOFF + c);
#define ACC_H(hv) { \
                float2 ha = __half22float2(*(half2*)&(hv).x), hb = __half22float2(*(half2*)&(hv).y); \
                a0 += ha.x; a1 += ha.y; a2 += hb.x; a3 += hb.y; }
                ACC_H(hv0) ACC_H(hv1) ACC_H(hv2) ACC_H(hv3)
            }
            for (; p < s1; p++) {
                unsigned int pe = g_csr[p];
                int2 hv = *(const int2*)(g_Af16 + (size_t)(pe & 0xFFFF) * KP + HOFF + c);
                ACC_H(hv)
            }
#undef ACC_H
        }
        float nm = norm[i];
        half2 o[2] = {__floats2half2_rn(a0 * nm, a1 * nm), __floats2half2_rn(a2 * nm, a3 * nm)};
        *(int2*)(g_Af16 + (size_t)i * KP + c) = *(int2*)o;
    } else {
        // prefix: compute rrelu(h_old @ Wevolve) for indeg==0 nodes
        __shared__ float sh[DD];
        int cnt = g_cnt[1];
        for (int j = blockIdx.x - AGG_B; j < cnt; j += PREF_B) {
            int r = g_list_no[j];
            for (int k = threadIdx.x; k < DD; k += blockDim.x)
                sh[k] = __half2float(g_Af16[(size_t)r * KP + HOFF + k]);
            __syncthreads();
            int c = threadIdx.x;
            if (c < DD) {
                float a = 0.f;
                for (int k = 0; k < DD; k++) a += sh[k] * wev[k * DD + c];
                a = a >= 0.f ? a : a * SLOPE;
                g_fixbuf[(size_t)j * DD + c] = a;
            }
            __syncthreads();
        }
    }
}

// ---------------- pipelined tensor-core GEMM (fp16 single pass) --------------
__global__ __launch_bounds__(256, 2) void gemm_mma(int layer, float* __restrict__ hout,
                                                   int write_next) {
    __shared__ __align__(16) __half sA[4][BM * 16];
    __shared__ __align__(16) __half sB[4][BN * 16];

    int tid = threadIdx.x;
    int lane = tid & 31, wid = tid >> 5;
    int wm = wid & 3, wn = wid >> 2;
    int m0 = blockIdx.x * BM;

    const __half* __restrict__ Bw = g_B16 + (size_t)layer * BN * KP;

    float acc[2][13][4];
#pragma unroll
    for (int i = 0; i < 2; i++)
#pragma unroll
        for (int j = 0; j < 13; j++)
#pragma unroll
            for (int q = 0; q < 4; q++) acc[i][j][q] = 0.f;

    int ar = tid >> 1, ah = tid & 1;
    long arow = m0 + ar; if (arow >= NN) arow = 0;
    size_t a_goff = (size_t)arow * KP + ah * 8;
    uint32_t a_sm = smem_u32(sA) + (uint32_t)(ar * 16 + 8 * (ah ^ ((ar >> 2) & 1))) * 2;

    int br0 = tid >> 1, bh0 = tid & 1;
    size_t b_goff0 = (size_t)br0 * KP + bh0 * 8;
    uint32_t b_sm0 = smem_u32(sB) + (uint32_t)(br0 * 16 + 8 * (bh0 ^ ((br0 >> 2) & 1))) * 2;
    int br1 = 128 + (tid >> 1), bh1 = tid & 1;
    size_t b_goff1 = (size_t)br1 * KP + bh1 * 8;
    uint32_t b_sm1 = smem_u32(sB) + (uint32_t)(br1 * 16 + 8 * (bh1 ^ ((br1 >> 2) & 1))) * 2;
    bool bp1 = tid < 160;

    auto issue = [&](int t) {
        int st = t & 3;
        long ko = (long)t * 16;
        cp16(a_sm + st * (BM * 16 * 2), g_Af16 + a_goff + ko);
        cp16(b_sm0 + st * (BN * 16 * 2), Bw + b_goff0 + ko);
        if (bp1) cp16(b_sm1 + st * (BN * 16 * 2), Bw + b_goff1 + ko);
        CP_COMMIT();
    };

    issue(0); issue(1); issue(2);

#pragma unroll 1
    for (int t = 0; t < NT; t++) {
        CP_WAIT2();
        __syncthreads();
        if (t + 3 < NT) issue(t + 3);

        int st = t & 3;
        uint32_t baseA = smem_u32(sA) + st * (BM * 16 * 2);
        uint32_t baseB = smem_u32(sB) + st * (BN * 16 * 2);
        uint32_t fa[2][4];
#pragma unroll
        for (int mi = 0; mi < 2; mi++) {
            int r = wm * 32 + mi * 16 + (lane & 15);
            int kh = lane >> 4;
            int off = r * 16 + 8 * (kh ^ ((r >> 2) & 1));
            ldsm4(fa[mi], baseA + off * 2);
        }
#pragma unroll
        for (int pj = 0; pj < 6; pj++) {
            int rB = wn * 104 + pj * 16 + (lane & 7) + ((lane & 16) ? 8 : 0);
            int kh = (lane >> 3) & 1;
            int off = rB * 16 + 8 * (kh ^ ((rB >> 2) & 1));
            uint32_t b[4];
            ldsm4(b, baseB + off * 2);
#pragma unroll
            for (int mi = 0; mi < 2; mi++) {
                mma16816(acc[mi][2 * pj], fa[mi], b[0], b[1]);
                mma16816(acc[mi][2 * pj + 1], fa[mi], b[2], b[3]);
            }
        }
        if (wn == 0) {   // tail cols 96..103; for wn==1 it's all padding
            int rB = 96 + (lane & 7) + ((lane & 16) ? 8 : 0);
            int kh = (lane >> 3) & 1;
            int off = rB * 16 + 8 * (kh ^ ((rB >> 2) & 1));
            uint32_t b[2];
            ldsm2(b, baseB + off * 2);
#pragma unroll
            for (int mi = 0; mi < 2; mi++)
                mma16816(acc[mi][12], fa[mi], b[0], b[1]);
        }
    }

    // epilogue: rrelu; write_next -> A fp16 h-region; hout -> fp32 out
    int gq = lane >> 2, tq = lane & 3;
#pragma unroll
    for (int mi = 0; mi < 2; mi++) {
        int row0 = m0 + wm * 32 + mi * 16 + gq;
        int row1 = row0 + 8;
#pragma unroll
        for (int nj = 0; nj < 13; nj++) {
            int col = wn * 104 + nj * 8 + tq * 2;
            if (col >= DD) continue;
            float v0 = acc[mi][nj][0], v1 = acc[mi][nj][1];
            float v2 = acc[mi][nj][2], v3 = acc[mi][nj][3];
            v0 = v0 >= 0.f ? v0 : v0 * SLOPE;
            v1 = v1 >= 0.f ? v1 : v1 * SLOPE;
            v2 = v2 >= 0.f ? v2 : v2 * SLOPE;
            v3 = v3 >= 0.f ? v3 : v3 * SLOPE;
            if (row0 < NN) {
                if (hout) *(float2*)(hout + (size_t)row0 * DD + col) = make_float2(v0, v1);
                if (write_next)
                    *(half2*)(g_Af16 + (size_t)row0 * KP + HOFF + col) = __floats2half2_rn(v0, v1);
            }
            if (row1 < NN) {
                if (hout) *(float2*)(hout + (size_t)row1 * DD + col) = make_float2(v2, v3);
                if (write_next)
                    *(half2*)(g_Af16 + (size_t)row1 * KP + HOFF + col) = __floats2half2_rn(v2, v3);
            }
        }
    }
}

// ---------------- indeg==0 scatter -------------------------------------------
__global__ void postfix_k(float* __restrict__ outbuf, int write_next) {
    int cnt = g_cnt[1];
    for (int j = blockIdx.x; j < cnt; j += gridDim.x) {
        int r = g_list_no[j];
        int c = threadIdx.x;
        if (c < DD) {
            float a = g_fixbuf[(size_t)j * DD + c];
            if (write_next) g_Af16[(size_t)r * KP + HOFF + c] = __float2half_rn(a);
            else            outbuf[(size_t)r * DD + c] = a;
        }
    }
}

// ---------------- launch -----------------------------------------------------
extern "C" void kernel_launch(void* const* d_in, const int* in_sizes, int n_in,
                              void* d_out, int out_size) {
    const float* init_emb = (const float*)d_in[0];
    const float* rel_emb  = (const float*)d_in[1];
    const float* w_neigh  = (const float*)d_in[2];
    const float* w_loop   = (const float*)d_in[3];
    const float* w_evolve = (const float*)d_in[4];
    const float* norm     = (const float*)d_in[5];
    const int*   src      = (const int*)d_in[6];
    const int*   dst      = (const int*)d_in[7];
    const int*   etype    = (const int*)d_in[8];
    const int*   node_id  = (const int*)d_in[9];
    float* out = (float*)d_out;

    count_k<<<(EE + 255) / 256, 256>>>(dst);                        // 0
    s1_k<<<NB, 256>>>();                                            // 1
    s2_k<<<1, 256>>>();                                             // 2
    s3_k<<<NB, 256>>>();                                            // 3
    setup_k<<<FILL_B + INIT_B + WPREP_B + RELC_B, 256>>>(           // 4
        src, dst, etype, init_emb, node_id, w_neigh, w_loop, rel_emb);

    int gtiles = (NN + BM - 1) / BM;

    agg_k<<<AGG_B + PREF_B, 256>>>(norm, 1, w_evolve + 0 * DD * DD); // 5
    gemm_mma<<<gtiles, 256>>>(0, (float*)nullptr, 1);                // 6
    postfix_k<<<PREF_B, 256>>>((float*)nullptr, 1);                  // 7

    agg_k<<<AGG_B + PREF_B, 256>>>(norm, 0, w_evolve + 1 * DD * DD); // 8
    gemm_mma<<<gtiles, 256>>>(1, out, 0);                            // 9
    postfix_k<<<PREF_B, 256>>>(out, 0);                              // 10
}

// round 16
// speedup vs baseline: 1.3975x; 1.3975x over previous
#include <cuda_runtime.h>
#include <cuda_fp16.h>
#include <cstdint>

#define NN 50000
#define EE 800000
#define DD 200
#define RR 500
#define KP 400           // fused K: [agg 0..199][h 200..399]
#define HOFF 200
#define BM 128
#define BN 208
#define NT 25            // 25 k-chunks (single fp16 pass)
#define SLOPE 0.22916666666666666f
#define NB 196           // ceil(NN/256)
#define AGG_B 12500      // ceil(NN/4): 4 nodes x 64 threads (warp-uniform)
#define PREF_B 16

// ---------------- scratch (zero-initialized at load; invariants restored) ----
__device__ __align__(16) __half g_Af16[(size_t)NN * KP];   // fp16 A: agg | h
__device__ __align__(16) __half g_B16[2 * BN * KP];        // fp16 weights (fused, transposed)
__device__ __align__(16) __half g_rel16[RR * DD];          // fp16 relation embeddings
__device__ float g_relagg[(size_t)NN * DD];                // fp32 (feeds both layers)
__device__ float g_fixbuf[(size_t)NN * DD];
__device__ int g_indeg[NN];          // zero at entry (restored by s3_k)
__device__ int g_off[NN + 1];
__device__ int g_cur[NN];
__device__ int g_exc[NN];
__device__ int g_bsum[NB];
__device__ int g_bpre[NB];
__device__ unsigned int g_csr[EE];   // src | (etype<<16)
__device__ int g_list_no[NN];
__device__ int g_cnt[2];             // zeroed by s2_k each call

// ---------------- helpers -----------------------------------------------------
__device__ __forceinline__ uint32_t smem_u32(const void* p) {
    uint32_t a;
    asm("{ .reg .u64 t; cvta.to.shared.u64 t, %1; cvt.u32.u64 %0, t; }" : "=r"(a) : "l"(p));
    return a;
}
__device__ __forceinline__ void cp16(uint32_t d, const void* s) {
    asm volatile("cp.async.cg.shared.global [%0], [%1], 16;" :: "r"(d), "l"(s));
}
#define CP_COMMIT() asm volatile("cp.async.commit_group;")
#define CP_WAIT2()  asm volatile("cp.async.wait_group 2;")
__device__ __forceinline__ void ldsm4(uint32_t* r, uint32_t a) {
    asm volatile("ldmatrix.sync.aligned.m8n8.x4.shared.b16 {%0,%1,%2,%3}, [%4];"
                 : "=r"(r[0]), "=r"(r[1]), "=r"(r[2]), "=r"(r[3]) : "r"(a));
}
__device__ __forceinline__ void ldsm2(uint32_t* r, uint32_t a) {
    asm volatile("ldmatrix.sync.aligned.m8n8.x2.shared.b16 {%0,%1}, [%2];"
                 : "=r"(r[0]), "=r"(r[1]) : "r"(a));
}
__device__ __forceinline__ void mma16816(float* c, const uint32_t* a, uint32_t b0, uint32_t b1) {
    asm volatile(
        "mma.sync.aligned.m16n8k16.row.col.f32.f16.f16.f32 "
        "{%0,%1,%2,%3},{%4,%5,%6,%7},{%8,%9},{%0,%1,%2,%3};"
        : "+f"(c[0]), "+f"(c[1]), "+f"(c[2]), "+f"(c[3])
        : "r"(a[0]), "r"(a[1]), "r"(a[2]), "r"(a[3]), "r"(b0), "r"(b1));
}

// ---------------- setup kernels ----------------------------------------------
__global__ void count_k(const int* __restrict__ dst) {
    int e = blockIdx.x * blockDim.x + threadIdx.x;
    if (e < EE) atomicAdd(&g_indeg[dst[e]], 1);
}
__global__ void s1_k() {
    int b = blockIdx.x, t = threadIdx.x, i = b * 256 + t;
    int v = (i < NN) ? g_indeg[i] : 0;
    int lane = t & 31, w = t >> 5;
    int x = v;
#pragma unroll
    for (int o = 1; o < 32; o <<= 1) {
        int y = __shfl_up_sync(0xffffffffu, x, o);
        if (lane >= o) x += y;
    }
    __shared__ int ws[8];
    if (lane == 31) ws[w] = x;
    __syncthreads();
    if (w == 0) {
        int s = (lane < 8) ? ws[lane] : 0;
#pragma unroll
        for (int o = 1; o < 8; o <<= 1) {
            int y = __shfl_up_sync(0xffffffffu, s, o);
            if (lane >= o) s += y;
        }
        if (lane < 8) ws[lane] = s;
    }
    __syncthreads();
    int incl = x + (w > 0 ? ws[w - 1] : 0);
    if (i < NN) g_exc[i] = incl - v;
    if (t == 255) g_bsum[b] = incl;
}
__global__ void s2_k() {
    int t = threadIdx.x;
    if (t < 2) g_cnt[t] = 0;
    int v = (t < NB) ? g_bsum[t] : 0;
    int lane = t & 31, w = t >> 5;
    int x = v;
#pragma unroll
    for (int o = 1; o < 32; o <<= 1) {
        int y = __shfl_up_sync(0xffffffffu, x, o);
        if (lane >= o) x += y;
    }
    __shared__ int ws[8];
    if (lane == 31) ws[w] = x;
    __syncthreads();
    if (w == 0) {
        int s = (lane < 8) ? ws[lane] : 0;
#pragma unroll
        for (int o = 1; o < 8; o <<= 1) {
            int y = __shfl_up_sync(0xffffffffu, s, o);
            if (lane >= o) s += y;
        }
        if (lane < 8) ws[lane] = s;
    }
    __syncthreads();
    int incl = x + (w > 0 ? ws[w - 1] : 0);
    if (t < NB) g_bpre[t] = incl - v;
    if (t == NB - 1) g_off[NN] = incl;
}
__global__ void s3_k() {
    int b = blockIdx.x, t = threadIdx.x, i = b * 256 + t;
    if (i >= NN) return;
    int o = g_exc[i] + g_bpre[b];
    g_off[i] = o;
    g_cur[i] = o;
    if (g_indeg[i] == 0) {
        int p = atomicAdd(&g_cnt[1], 1);
        g_list_no[p] = i;
    }
    g_indeg[i] = 0;   // restore invariant for next call
}
// fused: fill (CSR) + init (A h-region) + wprep (fp16 weights) + rel fp16
#define FILL_B 3125
#define INIT_B 19532
#define WPREP_B 650
#define RELC_B 196
__global__ void setup_k(const int* __restrict__ src, const int* __restrict__ dst,
                        const int* __restrict__ et,
                        const float* __restrict__ emb, const int* __restrict__ node_id,
                        const float* __restrict__ wn, const float* __restrict__ wl,
                        const float* __restrict__ rel) {
    int b = blockIdx.x;
    if (b < FILL_B) {
        int e = b * 256 + threadIdx.x;
        if (e < EE) {
            int p = atomicAdd(&g_cur[dst[e]], 1);
            g_csr[p] = (unsigned int)src[e] | ((unsigned int)et[e] << 16);
        }
    } else if (b < FILL_B + INIT_B) {
        long idx = (long)(b - FILL_B) * 256 + threadIdx.x;
        if (idx >= (long)NN * (DD / 2)) return;
        int i = (int)(idx / (DD / 2));
        int c = (int)(idx - (long)i * (DD / 2)) * 2;
        const float* e = emb + (size_t)node_id[i] * DD + c;
        *(half2*)(g_Af16 + (size_t)i * KP + HOFF + c) = __floats2half2_rn(e[0], e[1]);
    } else if (b < FILL_B + INIT_B + WPREP_B) {
        int idx = (b - FILL_B - INIT_B) * 256 + threadIdx.x;
        if (idx >= 2 * BN * KP) return;
        int l = idx / (BN * KP);
        int rem = idx - l * BN * KP;
        int n = rem / KP;
        int k = rem - n * KP;
        float w = 0.f;
        if (n < DD) {
            if (k < DD) w = wn[(size_t)l * DD * DD + k * DD + n];
            else        w = wl[(size_t)l * DD * DD + (k - DD) * DD + n];
        }
        g_B16[idx] = __float2half_rn(w);
    } else {
        int idx = (b - FILL_B - INIT_B - WPREP_B) * 256 + threadIdx.x;
        if (idx >= RR * DD / 2) return;
        int c = idx * 2;
        *(half2*)(g_rel16 + c) = __floats2half2_rn(rel[c], rel[c + 1]);
    }
}

// ---------------- aggregate (+ fused indeg==0 prefix) ------------------------
// 4 nodes per 256-thread block (warp-uniform: each 64-thread group = 1 node).
// 4-edge unrolled loop: loads batched (MLP=4), adds kept in edge order.
__global__ void agg_k(const float* __restrict__ norm, int first,
                      const float* __restrict__ wev) {
    if (blockIdx.x < AGG_B) {
        int sub = threadIdx.x >> 6;         // 0..3, warp-aligned node groups
        int tq = threadIdx.x & 63;
        int i = blockIdx.x * 4 + sub;
        if (i >= NN || tq >= DD / 4) return;
        int c = tq * 4;
        int s0 = g_off[i], s1 = g_off[i + 1];
        float a0 = 0.f, a1 = 0.f, a2 = 0.f, a3 = 0.f;
        if (first) {
            float r0 = 0.f, r1 = 0.f, r2 = 0.f, r3 = 0.f;
            int p = s0;
            for (; p + 4 <= s1; p += 4) {
                unsigned int pe0 = g_csr[p + 0], pe1 = g_csr[p + 1];
                unsigned int pe2 = g_csr[p + 2], pe3 = g_csr[p + 3];
                int2 rv0 = *(const int2*)(g_rel16 + (size_t)(pe0 >> 16) * DD + c);
                int2 rv1 = *(const int2*)(g_rel16 + (size_t)(pe1 >> 16) * DD + c);
                int2 rv2 = *(const int2*)(g_rel16 + (size_t)(pe2 >> 16) * DD + c);
                int2 rv3 = *(const int2*)(g_rel16 + (size_t)(pe3 >> 16) * DD + c);
                int2 hv0 = *(const int2*)(g_Af16 + (size_t)(pe0 & 0xFFFF) * KP + HOFF + c);
                int2 hv1 = *(const int2*)(g_Af16 + (size_t)(pe1 & 0xFFFF) * KP + HOFF + c);
                int2 hv2 = *(const int2*)(g_Af16 + (size_t)(pe2 & 0xFFFF) * KP + HOFF + c);
                int2 hv3 = *(const int2*)(g_Af16 + (size_t)(pe3 & 0xFFFF) * KP + HOFF + c);
#define ACC_RH(rv, hv) { \
                float2 ra = __half22float2(*(half2*)&(rv).x), rb = __half22float2(*(half2*)&(rv).y); \
                float2 ha = __half22float2(*(half2*)&(hv).x), hb = __half22float2(*(half2*)&(hv).y); \
                r0 += ra.x; r1 += ra.y; r2 += rb.x; r3 += rb.y; \
                a0 += ha.x; a1 += ha.y; a2 += hb.x; a3 += hb.y; }
                ACC_RH(rv0, hv0) ACC_RH(rv1, hv1) ACC_RH(rv2, hv2) ACC_RH(rv3, hv3)
            }
            for (; p < s1; p++) {
                unsigned int pe = g_csr[p];
                int2 rv = *(const int2*)(g_rel16 + (size_t)(pe >> 16) * DD + c);
                int2 hv = *(const int2*)(g_Af16 + (size_t)(pe & 0xFFFF) * KP + HOFF + c);
                ACC_RH(rv, hv)
            }
#undef ACC_RH
            *(float4*)(g_relagg + (size_t)i * DD + c) = make_float4(r0, r1, r2, r3);
            a0 += r0; a1 += r1; a2 += r2; a3 += r3;
        } else {
            float4 r4 = *(const float4*)(g_relagg + (size_t)i * DD + c);
            a0 = r4.x; a1 = r4.y; a2 = r4.z; a3 = r4.w;
            int p = s0;
            for (; p + 4 <= s1; p += 4) {
                unsigned int pe0 = g_csr[p + 0], pe1 = g_csr[p + 1];
                unsigned int pe2 = g_csr[p + 2], pe3 = g_csr[p + 3];
                int2 hv0 = *(const int2*)(g_Af16 + (size_t)(pe0 & 0xFFFF) * KP + HOFF + c);
                int2 hv1 = *(const int2*)(g_Af16 + (size_t)(pe1 & 0xFFFF) * KP + HOFF + c);
                int2 hv2 = *(const int2*)(g_Af16 + (size_t)(pe2 & 0xFFFF) * KP + HOFF + c);
                int2 hv3 = *(const int2*)(g_Af16 + (size_t)(pe3 & 0xFFFF) * KP + HOFF + c);
#define ACC_H(hv) { \
                float2 ha = __half22float2(*(half2*)&(hv).x), hb = __half22float2(*(half2*)&(hv).y); \
                a0 += ha.x; a1 += ha.y; a2 += hb.x; a3 += hb.y; }
                ACC_H(hv0) ACC_H(hv1) ACC_H(hv2) ACC_H(hv3)
            }
            for (; p < s1; p++) {
                unsigned int pe = g_csr[p];
                int2 hv = *(const int2*)(g_Af16 + (size_t)(pe & 0xFFFF) * KP + HOFF + c);
                ACC_H(hv)
            }
#undef ACC_H
        }
        float nm = norm[i];
        half2 o[2] = {__floats2half2_rn(a0 * nm, a1 * nm), __floats2half2_rn(a2 * nm, a3 * nm)};
        *(int2*)(g_Af16 + (size_t)i * KP + c) = *(int2*)o;
    } else {
        // prefix: compute rrelu(h_old @ Wevolve) for indeg==0 nodes
        __shared__ float sh[DD];
        int cnt = g_cnt[1];
        for (int j = blockIdx.x - AGG_B; j < cnt; j += PREF_B) {
            int r = g_list_no[j];
            for (int k = threadIdx.x; k < DD; k += blockDim.x)
                sh[k] = __half2float(g_Af16[(size_t)r * KP + HOFF + k]);
            __syncthreads();
            int c = threadIdx.x;
            if (c < DD) {
                float a = 0.f;
                for (int k = 0; k < DD; k++) a += sh[k] * wev[k * DD + c];
                a = a >= 0.f ? a : a * SLOPE;
                g_fixbuf[(size_t)j * DD + c] = a;
            }
            __syncthreads();
        }
    }
}

// ---------------- pipelined tensor-core GEMM (fp16 single pass) --------------
__global__ __launch_bounds__(256, 2) void gemm_mma(int layer, float* __restrict__ hout,
                                                   int write_next) {
    __shared__ __align__(16) __half sA[4][BM * 16];
    __shared__ __align__(16) __half sB[4][BN * 16];

    int tid = threadIdx.x;
    int lane = tid & 31, wid = tid >> 5;
    int wm = wid & 3, wn = wid >> 2;
    int m0 = blockIdx.x * BM;

    const __half* __restrict__ Bw = g_B16 + (size_t)layer * BN * KP;

    float acc[2][13][4];
#pragma unroll
    for (int i = 0; i < 2; i++)
#pragma unroll
        for (int j = 0; j < 13; j++)
#pragma unroll
            for (int q = 0; q < 4; q++) acc[i][j][q] = 0.f;

    int ar = tid >> 1, ah = tid & 1;
    long arow = m0 + ar; if (arow >= NN) arow = 0;
    size_t a_goff = (size_t)arow * KP + ah * 8;
    uint32_t a_sm = smem_u32(sA) + (uint32_t)(ar * 16 + 8 * (ah ^ ((ar >> 2) & 1))) * 2;

    int br0 = tid >> 1, bh0 = tid & 1;
    size_t b_goff0 = (size_t)br0 * KP + bh0 * 8;
    uint32_t b_sm0 = smem_u32(sB) + (uint32_t)(br0 * 16 + 8 * (bh0 ^ ((br0 >> 2) & 1))) * 2;
    int br1 = 128 + (tid >> 1), bh1 = tid & 1;
    size_t b_goff1 = (size_t)br1 * KP + bh1 * 8;
    uint32_t b_sm1 = smem_u32(sB) + (uint32_t)(br1 * 16 + 8 * (bh1 ^ ((br1 >> 2) & 1))) * 2;
    bool bp1 = tid < 160;

    auto issue = [&](int t) {
        int st = t & 3;
        long ko = (long)t * 16;
        cp16(a_sm + st * (BM * 16 * 2), g_Af16 + a_goff + ko);
        cp16(b_sm0 + st * (BN * 16 * 2), Bw + b_goff0 + ko);
        if (bp1) cp16(b_sm1 + st * (BN * 16 * 2), Bw + b_goff1 + ko);
        CP_COMMIT();
    };

    issue(0); issue(1); issue(2);

#pragma unroll 1
    for (int t = 0; t < NT; t++) {
        CP_WAIT2();
        __syncthreads();
        if (t + 3 < NT) issue(t + 3);

        int st = t & 3;
        uint32_t baseA = smem_u32(sA) + st * (BM * 16 * 2);
        uint32_t baseB = smem_u32(sB) + st * (BN * 16 * 2);
        uint32_t fa[2][4];
#pragma unroll
        for (int mi = 0; mi < 2; mi++) {
            int r = wm * 32 + mi * 16 + (lane & 15);
            int kh = lane >> 4;
            int off = r * 16 + 8 * (kh ^ ((r >> 2) & 1));
            ldsm4(fa[mi], baseA + off * 2);
        }
#pragma unroll
        for (int pj = 0; pj < 6; pj++) {
            int rB = wn * 104 + pj * 16 + (lane & 7) + ((lane & 16) ? 8 : 0);
            int kh = (lane >> 3) & 1;
            int off = rB * 16 + 8 * (kh ^ ((rB >> 2) & 1));
            uint32_t b[4];
            ldsm4(b, baseB + off * 2);
#pragma unroll
            for (int mi = 0; mi < 2; mi++) {
                mma16816(acc[mi][2 * pj], fa[mi], b[0], b[1]);
                mma16816(acc[mi][2 * pj + 1], fa[mi], b[2], b[3]);
            }
        }
        if (wn == 0) {   // tail cols 96..103; for wn==1 it's all padding
            int rB = 96 + (lane & 7) + ((lane & 16) ? 8 : 0);
            int kh = (lane >> 3) & 1;
            int off = rB * 16 + 8 * (kh ^ ((rB >> 2) & 1));
            uint32_t b[2];
            ldsm2(b, baseB + off * 2);
#pragma unroll
            for (int mi = 0; mi < 2; mi++)
                mma16816(acc[mi][12], fa[mi], b[0], b[1]);
        }
    }

    // epilogue: rrelu; write_next -> A fp16 h-region; hout -> fp32 out
    int gq = lane >> 2, tq = lane & 3;
#pragma unroll
    for (int mi = 0; mi < 2; mi++) {
        int row0 = m0 + wm * 32 + mi * 16 + gq;
        int row1 = row0 + 8;
#pragma unroll
        for (int nj = 0; nj < 13; nj++) {
            int col = wn * 104 + nj * 8 + tq * 2;
            if (col >= DD) continue;
            float v0 = acc[mi][nj][0], v1 = acc[mi][nj][1];
            float v2 = acc[mi][nj][2], v3 = acc[mi][nj][3];
            v0 = v0 >= 0.f ? v0 : v0 * SLOPE;
            v1 = v1 >= 0.f ? v1 : v1 * SLOPE;
            v2 = v2 >= 0.f ? v2 : v2 * SLOPE;
            v3 = v3 >= 0.f ? v3 : v3 * SLOPE;
            if (row0 < NN) {
                if (hout) *(float2*)(hout + (size_t)row0 * DD + col) = make_float2(v0, v1);
                if (write_next)
                    *(half2*)(g_Af16 + (size_t)row0 * KP + HOFF + col) = __floats2half2_rn(v0, v1);
            }
            if (row1 < NN) {
                if (hout) *(float2*)(hout + (size_t)row1 * DD + col) = make_float2(v2, v3);
                if (write_next)
                    *(half2*)(g_Af16 + (size_t)row1 * KP + HOFF + col) = __floats2half2_rn(v2, v3);
            }
        }
    }
}

// ---------------- indeg==0 scatter -------------------------------------------
__global__ void postfix_k(float* __restrict__ outbuf, int write_next) {
    int cnt = g_cnt[1];
    for (int j = blockIdx.x; j < cnt; j += gridDim.x) {
        int r = g_list_no[j];
        int c = threadIdx.x;
        if (c < DD) {
            float a = g_fixbuf[(size_t)j * DD + c];
            if (write_next) g_Af16[(size_t)r * KP + HOFF + c] = __float2half_rn(a);
            else            outbuf[(size_t)r * DD + c] = a;
        }
    }
}

// ---------------- launch -----------------------------------------------------
extern "C" void kernel_launch(void* const* d_in, const int* in_sizes, int n_in,
                              void* d_out, int out_size) {
    const float* init_emb = (const float*)d_in[0];
    const float* rel_emb  = (const float*)d_in[1];
    const float* w_neigh  = (const float*)d_in[2];
    const float* w_loop   = (const float*)d_in[3];
    const float* w_evolve = (const float*)d_in[4];
    const float* norm     = (const float*)d_in[5];
    const int*   src      = (const int*)d_in[6];
    const int*   dst      = (const int*)d_in[7];
    const int*   etype    = (const int*)d_in[8];
    const int*   node_id  = (const int*)d_in[9];
    float* out = (float*)d_out;

    count_k<<<(EE + 255) / 256, 256>>>(dst);                        // 0
    s1_k<<<NB, 256>>>();                                            // 1
    s2_k<<<1, 256>>>();                                             // 2
    s3_k<<<NB, 256>>>();                                            // 3
    setup_k<<<FILL_B + INIT_B + WPREP_B + RELC_B, 256>>>(           // 4
        src, dst, etype, init_emb, node_id, w_neigh, w_loop, rel_emb);

    int gtiles = (NN + BM - 1) / BM;

    agg_k<<<AGG_B + PREF_B, 256>>>(norm, 1, w_evolve + 0 * DD * DD); // 5
    gemm_mma<<<gtiles, 256>>>(0, (float*)nullptr, 1);                // 6
    postfix_k<<<PREF_B, 256>>>((float*)nullptr, 1);                  // 7

    agg_k<<<AGG_B + PREF_B, 256>>>(norm, 0, w_evolve + 1 * DD * DD); // 8
    gemm_mma<<<gtiles, 256>>>(1, out, 0);                            // 9
    postfix_k<<<PREF_B, 256>>>(out, 0);                              // 10
}